// round 10
// baseline (speedup 1.0000x reference)
#include <cuda_runtime.h>

#define EPS_BN 1e-5f

typedef unsigned long long ull;

// Scratch (static device arrays; no allocation allowed)
__device__ float g_trans[2 * 8 * 256 * 256];  // [tensor][b][o][n] conv1 output (post BN+ReLU)
__device__ float g_pm[4096 * 2];              // per (row, n-half) softmax partial: max
__device__ float g_ps1[4096 * 2];             // partial sum exp
__device__ float g_ps2[4096 * 2];             // partial sum (x-m)exp
__device__ float g_ew[8 * 256];               // sigmoid entropy gate
__device__ float g_mw[8 * 256];               // sigmoid mi gate

__device__ __forceinline__ float sigmoidf(float x) {
    return 1.f / (1.f + __expf(-x));
}

// ---- packed fp32x2 helpers --------------------------------------------------
__device__ __forceinline__ ull pk2(float x) {
    ull r;
    asm("mov.b64 %0, {%1, %1};" : "=l"(r) : "f"(x));
    return r;
}
__device__ __forceinline__ void fma2(ull& d, ull a, ull b) {
    asm("fma.rn.f32x2 %0, %1, %2, %0;" : "+l"(d) : "l"(a), "l"(b));
}
__device__ __forceinline__ float2 upk(ull v) {
    float2 r;
    asm("mov.b64 {%0, %1}, %2;" : "=f"(r.x), "=f"(r.y) : "l"(v));
    return r;
}

// ---------------------------------------------------------------------------
// K1: conv1 (1x1 conv GEMM) + BN + ReLU + fused per-half-row softmax partials.
// Tile 64(M) x 128(N), 256 threads, per-thread 4x8 via f32x2, K=256,
// register-staged double buffer. Grid (4,2,16) = 128 blocks.
// Epilogue: each 16-lane group owns 4 full 128-wide half-rows; computes
// (max, sum e^{x-m}, sum (x-m)e^{x-m}) and writes them to g_pm/g_ps1/g_ps2.
// ---------------------------------------------------------------------------
__global__ __launch_bounds__(256) void conv1_kernel(
    const float* __restrict__ vis, const float* __restrict__ text,
    const float* __restrict__ W, const float* __restrict__ bt,
    const float* __restrict__ g1, const float* __restrict__ b1,
    const float* __restrict__ m1, const float* __restrict__ v1)
{
    __shared__ __align__(16) float As[2][8][72];
    __shared__ __align__(16) float Bs[2][8][128];

    const int bm = blockIdx.x * 64;
    const int bn = blockIdx.y * 128;
    const int half = blockIdx.y;
    const int zb = blockIdx.z;
    const int tensor = zb >> 3, b = zb & 7;
    const float* __restrict__ X = (tensor ? text : vis) + b * 65536;

    const int tid = threadIdx.x;
    const int tx = tid & 15, ty = tid >> 4;

    const int iA = tid >> 3, jA = tid & 7;
    const float* __restrict__ pA0 = W + (bm + iA) * 256 + jA;
    const int nB = tid & 127, jB = tid >> 7;
    const float* __restrict__ pB0 = X + jB * 256 + bn + nB;

    float ra0, ra1, rb0, rb1, rb2, rb3;

    ra0 = pA0[0];       ra1 = pA0[32 * 256];
    rb0 = pB0[0];       rb1 = pB0[2 * 256];
    rb2 = pB0[4 * 256]; rb3 = pB0[6 * 256];
    As[0][jA][iA] = ra0; As[0][jA][iA + 32] = ra1;
    Bs[0][jB][nB] = rb0; Bs[0][jB + 2][nB] = rb1;
    Bs[0][jB + 4][nB] = rb2; Bs[0][jB + 6][nB] = rb3;
    __syncthreads();

    ull acc[4][4];
    #pragma unroll
    for (int r = 0; r < 4; r++)
        #pragma unroll
        for (int p = 0; p < 4; p++) acc[r][p] = 0ull;

    int buf = 0;
    for (int step = 0; step < 32; step++) {
        const int c0n = (step + 1) * 8;
        if (step < 31) {
            ra0 = pA0[c0n];            ra1 = pA0[32 * 256 + c0n];
            const float* pb = pB0 + c0n * 256;
            rb0 = pb[0];    rb1 = pb[512];
            rb2 = pb[1024]; rb3 = pb[1536];
        }
        #pragma unroll
        for (int kk = 0; kk < 8; kk++) {
            const float4 a4 = *(const float4*)&As[buf][kk][ty * 4];
            const ull ad0 = pk2(a4.x), ad1 = pk2(a4.y), ad2 = pk2(a4.z), ad3 = pk2(a4.w);
            const ulonglong2 bA = *(const ulonglong2*)&Bs[buf][kk][tx * 8];
            const ulonglong2 bB = *(const ulonglong2*)&Bs[buf][kk][tx * 8 + 4];
            fma2(acc[0][0], ad0, bA.x); fma2(acc[0][1], ad0, bA.y);
            fma2(acc[0][2], ad0, bB.x); fma2(acc[0][3], ad0, bB.y);
            fma2(acc[1][0], ad1, bA.x); fma2(acc[1][1], ad1, bA.y);
            fma2(acc[1][2], ad1, bB.x); fma2(acc[1][3], ad1, bB.y);
            fma2(acc[2][0], ad2, bA.x); fma2(acc[2][1], ad2, bA.y);
            fma2(acc[2][2], ad2, bB.x); fma2(acc[2][3], ad2, bB.y);
            fma2(acc[3][0], ad3, bA.x); fma2(acc[3][1], ad3, bA.y);
            fma2(acc[3][2], ad3, bB.x); fma2(acc[3][3], ad3, bB.y);
        }
        if (step < 31) {
            const int nb = buf ^ 1;
            As[nb][jA][iA] = ra0; As[nb][jA][iA + 32] = ra1;
            Bs[nb][jB][nB] = rb0; Bs[nb][jB + 2][nB] = rb1;
            Bs[nb][jB + 4][nB] = rb2; Bs[nb][jB + 6][nB] = rb3;
        }
        __syncthreads();
        buf ^= 1;
    }

    #pragma unroll
    for (int r = 0; r < 4; r++) {
        const int orow = bm + ty * 4 + r;
        const float s = g1[orow] * rsqrtf(v1[orow] + EPS_BN);
        const float sh = (bt[orow] - m1[orow]) * s + b1[orow];
        float y[8];
        #pragma unroll
        for (int p = 0; p < 4; p++) {
            float2 v = upk(acc[r][p]);
            y[2 * p] = fmaxf(v.x * s + sh, 0.f);
            y[2 * p + 1] = fmaxf(v.y * s + sh, 0.f);
        }
        float* dst = &g_trans[(zb * 256 + orow) * 256 + bn + tx * 8];
        *(float4*)dst = make_float4(y[0], y[1], y[2], y[3]);
        *(float4*)(dst + 4) = make_float4(y[4], y[5], y[6], y[7]);

        // online-softmax partial over this 128-wide half-row (16 lanes x 8 vals)
        float mx = y[0];
        #pragma unroll
        for (int p = 1; p < 8; p++) mx = fmaxf(mx, y[p]);
        #pragma unroll
        for (int off = 8; off; off >>= 1) mx = fmaxf(mx, __shfl_xor_sync(0xffffffffu, mx, off));
        float s1 = 0.f, s2 = 0.f;
        #pragma unroll
        for (int p = 0; p < 8; p++) {
            float u = y[p] - mx;
            float e = __expf(u);
            s1 += e;
            s2 += u * e;
        }
        #pragma unroll
        for (int off = 8; off; off >>= 1) {
            s1 += __shfl_xor_sync(0xffffffffu, s1, off);
            s2 += __shfl_xor_sync(0xffffffffu, s2, off);
        }
        if (tx == 0) {
            int idx = (zb * 256 + orow) * 2 + half;
            g_pm[idx] = mx;
            g_ps1[idx] = s1;
            g_ps2[idx] = s2;
        }
    }
}

// ---------------------------------------------------------------------------
// Merge two softmax partials -> A = sum p*ln p = S2/S1 - ln S1 (exact LSE merge)
// ---------------------------------------------------------------------------
__device__ __forceinline__ float mergeA(int r2)
{
    float m0 = g_pm[r2], m1 = g_pm[r2 + 1];
    float a0 = g_ps1[r2], a1 = g_ps1[r2 + 1];
    float c0 = g_ps2[r2], c1 = g_ps2[r2 + 1];
    float M = fmaxf(m0, m1);
    float e0 = __expf(m0 - M), e1 = __expf(m1 - M);
    float S1 = a0 * e0 + a1 * e1;
    float S2 = (c0 + (m0 - M) * a0) * e0 + (c1 + (m1 - M) * a1) * e1;
    return S2 / S1 - logf(S1);
}

// ---------------------------------------------------------------------------
// K2: gates kernel. Grid 16 = (branch, batch); 512 threads.
// branch 0: entropy chain  -A concat -> We1/relu -> We2/sigmoid -> g_ew
// branch 1: mi chain       A_v+A_t   -> Wm1/relu -> Wm2/sigmoid -> g_mw
// Each warp computes 16 outputs with batched accumulators (high ILP).
// ---------------------------------------------------------------------------
__global__ __launch_bounds__(512) void gates_kernel(
    const float* __restrict__ We1, const float* __restrict__ be1,
    const float* __restrict__ We2, const float* __restrict__ be2,
    const float* __restrict__ Wm1, const float* __restrict__ bm1,
    const float* __restrict__ Wm2, const float* __restrict__ bm2)
{
    __shared__ float xs[512];
    __shared__ float h1[256];

    const int bid = blockIdx.x;
    const int branch = bid >> 3;
    const int b = bid & 7;
    const int tid = threadIdx.x;
    const int warp = tid >> 5, lane = tid & 31;

    if (tid < 256) {
        const int c = tid;
        float Av = mergeA((b * 256 + c) * 2);
        float At = mergeA(((8 + b) * 256 + c) * 2);
        if (branch == 0) {
            xs[c] = -Av;
            xs[256 + c] = -At;
        } else {
            xs[c] = Av + At;
        }
    }
    __syncthreads();

    const int j0 = warp * 16;

    // ---- layer 1 ----
    {
        const float* __restrict__ W1 = branch ? Wm1 : We1;
        const float* __restrict__ bb1 = branch ? bm1 : be1;
        float acc[16];
        #pragma unroll
        for (int q = 0; q < 16; q++) acc[q] = 0.f;
        if (branch == 0) {
            #pragma unroll
            for (int i = 0; i < 16; i++) {
                float x = xs[lane + 32 * i];
                #pragma unroll
                for (int q = 0; q < 16; q++)
                    acc[q] += W1[(j0 + q) * 512 + lane + 32 * i] * x;
            }
        } else {
            #pragma unroll
            for (int i = 0; i < 8; i++) {
                float x = xs[lane + 32 * i];
                #pragma unroll
                for (int q = 0; q < 16; q++)
                    acc[q] += W1[(j0 + q) * 256 + lane + 32 * i] * x;
            }
        }
        #pragma unroll
        for (int q = 0; q < 16; q++)
            #pragma unroll
            for (int off = 16; off; off >>= 1)
                acc[q] += __shfl_xor_sync(0xffffffffu, acc[q], off);
        if (lane == 0) {
            #pragma unroll
            for (int q = 0; q < 16; q++)
                h1[j0 + q] = fmaxf(acc[q] + bb1[j0 + q], 0.f);
        }
    }
    __syncthreads();

    // ---- layer 2 + sigmoid ----
    {
        const float* __restrict__ W2 = branch ? Wm2 : We2;
        const float* __restrict__ bb2 = branch ? bm2 : be2;
        float acc[16];
        #pragma unroll
        for (int q = 0; q < 16; q++) acc[q] = 0.f;
        #pragma unroll
        for (int i = 0; i < 8; i++) {
            float x = h1[lane + 32 * i];
            #pragma unroll
            for (int q = 0; q < 16; q++)
                acc[q] += W2[(j0 + q) * 256 + lane + 32 * i] * x;
        }
        #pragma unroll
        for (int q = 0; q < 16; q++)
            #pragma unroll
            for (int off = 16; off; off >>= 1)
                acc[q] += __shfl_xor_sync(0xffffffffu, acc[q], off);
        if (lane == 0) {
            float* out = branch ? g_mw : g_ew;
            #pragma unroll
            for (int q = 0; q < 16; q++)
                out[b * 256 + j0 + q] = sigmoidf(acc[q] + bb2[j0 + q]);
        }
    }
}

// ---------------------------------------------------------------------------
// K4: final conv, K=512 (vis half then text half), gates folded into B staging.
// Tile 64x64, 128 threads, per-thread 4x8 (f32x2), double-buffered.
// Grid (4,4,8) = 128 blocks. LDS ratio 1.5 (vs 2.0 before).
// ---------------------------------------------------------------------------
__global__ __launch_bounds__(128) void conv2_kernel(
    const float* __restrict__ Wf, const float* __restrict__ bf,
    const float* __restrict__ g2, const float* __restrict__ b2,
    const float* __restrict__ m2, const float* __restrict__ v2,
    float* __restrict__ out)
{
    __shared__ __align__(16) float As[2][8][72];
    __shared__ __align__(16) float Bs[2][8][64];
    __shared__ float sc[512];

    const int bm = blockIdx.x * 64;
    const int bn = blockIdx.y * 64;
    const int b = blockIdx.z;
    const int tid = threadIdx.x;
    const int tx = tid & 7, ty = tid >> 3;  // tx: 8 col-groups, ty: 16 row-groups

    #pragma unroll
    for (int l = tid; l < 256; l += 128) {
        float e = g_ew[b * 256 + l], m = g_mw[b * 256 + l];
        sc[l] = e * m;
        sc[l + 256] = (1.f - e) * m;
    }

    // A staging: thread -> (iA, kA): float4 along K
    const int iA = tid >> 1, kA = (tid & 1) * 4;
    const float* __restrict__ pA0 = Wf + (bm + iA) * 512 + kA;
    // B staging: thread -> (jB, nB): k-rows jB, jB+2, jB+4, jB+6
    const int nB = tid & 63, jB = tid >> 6;
    const float* __restrict__ Xv = g_trans + b * 65536 + bn + nB;
    const float* __restrict__ Xt = g_trans + (8 + b) * 65536 + bn + nB;

    float4 ra;
    float rb0, rb1, rb2, rb3;

    ra = *(const float4*)pA0;
    rb0 = Xv[jB * 256];       rb1 = Xv[(jB + 2) * 256];
    rb2 = Xv[(jB + 4) * 256]; rb3 = Xv[(jB + 6) * 256];
    __syncthreads();  // sc ready before use below
    As[0][kA][iA] = ra.x; As[0][kA + 1][iA] = ra.y;
    As[0][kA + 2][iA] = ra.z; As[0][kA + 3][iA] = ra.w;
    Bs[0][jB][nB] = rb0 * sc[jB];
    Bs[0][jB + 2][nB] = rb1 * sc[jB + 2];
    Bs[0][jB + 4][nB] = rb2 * sc[jB + 4];
    Bs[0][jB + 6][nB] = rb3 * sc[jB + 6];
    __syncthreads();

    ull acc[4][4];
    #pragma unroll
    for (int r = 0; r < 4; r++)
        #pragma unroll
        for (int p = 0; p < 4; p++) acc[r][p] = 0ull;

    int buf = 0;
    for (int step = 0; step < 64; step++) {
        const int c0n = (step + 1) * 8;
        if (step < 63) {
            ra = *(const float4*)(pA0 + c0n);
            const float* pb = (c0n < 256) ? (Xv + c0n * 256) : (Xt + (c0n - 256) * 256);
            rb0 = pb[jB * 256];       rb1 = pb[(jB + 2) * 256];
            rb2 = pb[(jB + 4) * 256]; rb3 = pb[(jB + 6) * 256];
        }
        #pragma unroll
        for (int kk = 0; kk < 8; kk++) {
            const float4 a4 = *(const float4*)&As[buf][kk][ty * 4];
            const ull ad0 = pk2(a4.x), ad1 = pk2(a4.y), ad2 = pk2(a4.z), ad3 = pk2(a4.w);
            const ulonglong2 bA = *(const ulonglong2*)&Bs[buf][kk][tx * 8];
            const ulonglong2 bB = *(const ulonglong2*)&Bs[buf][kk][tx * 8 + 4];
            fma2(acc[0][0], ad0, bA.x); fma2(acc[0][1], ad0, bA.y);
            fma2(acc[0][2], ad0, bB.x); fma2(acc[0][3], ad0, bB.y);
            fma2(acc[1][0], ad1, bA.x); fma2(acc[1][1], ad1, bA.y);
            fma2(acc[1][2], ad1, bB.x); fma2(acc[1][3], ad1, bB.y);
            fma2(acc[2][0], ad2, bA.x); fma2(acc[2][1], ad2, bA.y);
            fma2(acc[2][2], ad2, bB.x); fma2(acc[2][3], ad2, bB.y);
            fma2(acc[3][0], ad3, bA.x); fma2(acc[3][1], ad3, bA.y);
            fma2(acc[3][2], ad3, bB.x); fma2(acc[3][3], ad3, bB.y);
        }
        if (step < 63) {
            const int nb = buf ^ 1;
            As[nb][kA][iA] = ra.x; As[nb][kA + 1][iA] = ra.y;
            As[nb][kA + 2][iA] = ra.z; As[nb][kA + 3][iA] = ra.w;
            Bs[nb][jB][nB] = rb0 * sc[c0n + jB];
            Bs[nb][jB + 2][nB] = rb1 * sc[c0n + jB + 2];
            Bs[nb][jB + 4][nB] = rb2 * sc[c0n + jB + 4];
            Bs[nb][jB + 6][nB] = rb3 * sc[c0n + jB + 6];
        }
        __syncthreads();
        buf ^= 1;
    }

    #pragma unroll
    for (int r = 0; r < 4; r++) {
        const int o = bm + ty * 4 + r;
        const float s = g2[o] * rsqrtf(v2[o] + EPS_BN);
        const float sh = (bf[o] - m2[o]) * s + b2[o];
        float y[8];
        #pragma unroll
        for (int p = 0; p < 4; p++) {
            float2 v = upk(acc[r][p]);
            y[2 * p] = fmaxf(v.x * s + sh, 0.f);
            y[2 * p + 1] = fmaxf(v.y * s + sh, 0.f);
        }
        float* dst = &out[(b * 256 + o) * 256 + bn + tx * 8];
        *(float4*)dst = make_float4(y[0], y[1], y[2], y[3]);
        *(float4*)(dst + 4) = make_float4(y[4], y[5], y[6], y[7]);
    }
}

// ---------------------------------------------------------------------------
extern "C" void kernel_launch(void* const* d_in, const int* in_sizes, int n_in,
                              void* d_out, int out_size)
{
    const float* vis  = (const float*)d_in[0];
    const float* text = (const float*)d_in[1];
    const float* Wt   = (const float*)d_in[2];
    const float* bt   = (const float*)d_in[3];
    const float* g1   = (const float*)d_in[4];
    const float* b1   = (const float*)d_in[5];
    const float* m1   = (const float*)d_in[6];
    const float* v1   = (const float*)d_in[7];
    const float* We1  = (const float*)d_in[8];
    const float* be1  = (const float*)d_in[9];
    const float* We2  = (const float*)d_in[10];
    const float* be2  = (const float*)d_in[11];
    const float* Wm1  = (const float*)d_in[12];
    const float* bm1  = (const float*)d_in[13];
    const float* Wm2  = (const float*)d_in[14];
    const float* bm2  = (const float*)d_in[15];
    const float* Wf   = (const float*)d_in[16];
    const float* bf   = (const float*)d_in[17];
    const float* g2   = (const float*)d_in[18];
    const float* b2   = (const float*)d_in[19];
    const float* m2   = (const float*)d_in[20];
    const float* v2   = (const float*)d_in[21];
    float* out = (float*)d_out;

    conv1_kernel<<<dim3(4, 2, 16), 256>>>(vis, text, Wt, bt, g1, b1, m1, v1);
    gates_kernel<<<16, 512>>>(We1, be1, We2, be2, Wm1, bm1, Wm2, bm2);
    conv2_kernel<<<dim3(4, 4, 8), 128>>>(Wf, bf, g2, b2, m2, v2, out);
}

// round 12
// speedup vs baseline: 1.0028x; 1.0028x over previous
#include <cuda_runtime.h>

#define EPS_BN 1e-5f

typedef unsigned long long ull;

// Scratch (static device arrays; no allocation allowed)
__device__ float g_trans[2 * 8 * 256 * 256];  // [tensor][b][o][n] conv1 output (post BN+ReLU)
__device__ float g_pm[4096 * 2];              // per (row, n-half) softmax partial: max
__device__ float g_ps1[4096 * 2];             // partial sum exp
__device__ float g_ps2[4096 * 2];             // partial sum (x-m)exp
__device__ float g_ew[8 * 256];               // sigmoid entropy gate
__device__ float g_mw[8 * 256];               // sigmoid mi gate

__device__ __forceinline__ float sigmoidf(float x) {
    return 1.f / (1.f + __expf(-x));
}

// ---- packed fp32x2 helpers --------------------------------------------------
__device__ __forceinline__ ull pk2(float x) {
    ull r;
    asm("mov.b64 %0, {%1, %1};" : "=l"(r) : "f"(x));
    return r;
}
__device__ __forceinline__ void fma2(ull& d, ull a, ull b) {
    asm("fma.rn.f32x2 %0, %1, %2, %0;" : "+l"(d) : "l"(a), "l"(b));
}
__device__ __forceinline__ float2 upk(ull v) {
    float2 r;
    asm("mov.b64 {%0, %1}, %2;" : "=f"(r.x), "=f"(r.y) : "l"(v));
    return r;
}

// ---------------------------------------------------------------------------
// K1: conv1 (1x1 conv GEMM) + BN + ReLU + fused per-half-row softmax partials.
// Tile 64(M) x 128(N), 256 threads, per-thread 4x8 via f32x2, K=256,
// register-staged double buffer. Grid (4,2,16) = 128 blocks.
// Epilogue: each 16-lane group owns 4 full 128-wide half-rows; computes
// (max, sum e^{x-m}, sum (x-m)e^{x-m}) and writes them to g_pm/g_ps1/g_ps2.
// ---------------------------------------------------------------------------
__global__ __launch_bounds__(256) void conv1_kernel(
    const float* __restrict__ vis, const float* __restrict__ text,
    const float* __restrict__ W, const float* __restrict__ bt,
    const float* __restrict__ g1, const float* __restrict__ b1,
    const float* __restrict__ m1, const float* __restrict__ v1)
{
    __shared__ __align__(16) float As[2][8][72];
    __shared__ __align__(16) float Bs[2][8][128];

    const int bm = blockIdx.x * 64;
    const int bn = blockIdx.y * 128;
    const int half = blockIdx.y;
    const int zb = blockIdx.z;
    const int tensor = zb >> 3, b = zb & 7;
    const float* __restrict__ X = (tensor ? text : vis) + b * 65536;

    const int tid = threadIdx.x;
    const int tx = tid & 15, ty = tid >> 4;

    const int iA = tid >> 3, jA = tid & 7;
    const float* __restrict__ pA0 = W + (bm + iA) * 256 + jA;
    const int nB = tid & 127, jB = tid >> 7;
    const float* __restrict__ pB0 = X + jB * 256 + bn + nB;

    float ra0, ra1, rb0, rb1, rb2, rb3;

    ra0 = pA0[0];       ra1 = pA0[32 * 256];
    rb0 = pB0[0];       rb1 = pB0[2 * 256];
    rb2 = pB0[4 * 256]; rb3 = pB0[6 * 256];
    As[0][jA][iA] = ra0; As[0][jA][iA + 32] = ra1;
    Bs[0][jB][nB] = rb0; Bs[0][jB + 2][nB] = rb1;
    Bs[0][jB + 4][nB] = rb2; Bs[0][jB + 6][nB] = rb3;
    __syncthreads();

    ull acc[4][4];
    #pragma unroll
    for (int r = 0; r < 4; r++)
        #pragma unroll
        for (int p = 0; p < 4; p++) acc[r][p] = 0ull;

    int buf = 0;
    for (int step = 0; step < 32; step++) {
        const int c0n = (step + 1) * 8;
        if (step < 31) {
            ra0 = pA0[c0n];            ra1 = pA0[32 * 256 + c0n];
            const float* pb = pB0 + c0n * 256;
            rb0 = pb[0];    rb1 = pb[512];
            rb2 = pb[1024]; rb3 = pb[1536];
        }
        #pragma unroll
        for (int kk = 0; kk < 8; kk++) {
            const float4 a4 = *(const float4*)&As[buf][kk][ty * 4];
            const ull ad0 = pk2(a4.x), ad1 = pk2(a4.y), ad2 = pk2(a4.z), ad3 = pk2(a4.w);
            const ulonglong2 bA = *(const ulonglong2*)&Bs[buf][kk][tx * 8];
            const ulonglong2 bB = *(const ulonglong2*)&Bs[buf][kk][tx * 8 + 4];
            fma2(acc[0][0], ad0, bA.x); fma2(acc[0][1], ad0, bA.y);
            fma2(acc[0][2], ad0, bB.x); fma2(acc[0][3], ad0, bB.y);
            fma2(acc[1][0], ad1, bA.x); fma2(acc[1][1], ad1, bA.y);
            fma2(acc[1][2], ad1, bB.x); fma2(acc[1][3], ad1, bB.y);
            fma2(acc[2][0], ad2, bA.x); fma2(acc[2][1], ad2, bA.y);
            fma2(acc[2][2], ad2, bB.x); fma2(acc[2][3], ad2, bB.y);
            fma2(acc[3][0], ad3, bA.x); fma2(acc[3][1], ad3, bA.y);
            fma2(acc[3][2], ad3, bB.x); fma2(acc[3][3], ad3, bB.y);
        }
        if (step < 31) {
            const int nb = buf ^ 1;
            As[nb][jA][iA] = ra0; As[nb][jA][iA + 32] = ra1;
            Bs[nb][jB][nB] = rb0; Bs[nb][jB + 2][nB] = rb1;
            Bs[nb][jB + 4][nB] = rb2; Bs[nb][jB + 6][nB] = rb3;
        }
        __syncthreads();
        buf ^= 1;
    }

    #pragma unroll
    for (int r = 0; r < 4; r++) {
        const int orow = bm + ty * 4 + r;
        const float s = g1[orow] * rsqrtf(v1[orow] + EPS_BN);
        const float sh = (bt[orow] - m1[orow]) * s + b1[orow];
        float y[8];
        #pragma unroll
        for (int p = 0; p < 4; p++) {
            float2 v = upk(acc[r][p]);
            y[2 * p] = fmaxf(v.x * s + sh, 0.f);
            y[2 * p + 1] = fmaxf(v.y * s + sh, 0.f);
        }
        float* dst = &g_trans[(zb * 256 + orow) * 256 + bn + tx * 8];
        *(float4*)dst = make_float4(y[0], y[1], y[2], y[3]);
        *(float4*)(dst + 4) = make_float4(y[4], y[5], y[6], y[7]);

        // online-softmax partial over this 128-wide half-row (16 lanes x 8 vals)
        float mx = y[0];
        #pragma unroll
        for (int p = 1; p < 8; p++) mx = fmaxf(mx, y[p]);
        #pragma unroll
        for (int off = 8; off; off >>= 1) mx = fmaxf(mx, __shfl_xor_sync(0xffffffffu, mx, off));
        float s1 = 0.f, s2 = 0.f;
        #pragma unroll
        for (int p = 0; p < 8; p++) {
            float u = y[p] - mx;
            float e = __expf(u);
            s1 += e;
            s2 += u * e;
        }
        #pragma unroll
        for (int off = 8; off; off >>= 1) {
            s1 += __shfl_xor_sync(0xffffffffu, s1, off);
            s2 += __shfl_xor_sync(0xffffffffu, s2, off);
        }
        if (tx == 0) {
            int idx = (zb * 256 + orow) * 2 + half;
            g_pm[idx] = mx;
            g_ps1[idx] = s1;
            g_ps2[idx] = s2;
        }
    }
}

// ---------------------------------------------------------------------------
// Merge two softmax partials -> A = sum p*ln p = S2/S1 - ln S1 (exact LSE merge)
// ---------------------------------------------------------------------------
__device__ __forceinline__ float mergeA(int r2)
{
    float m0 = g_pm[r2], m1 = g_pm[r2 + 1];
    float a0 = g_ps1[r2], a1 = g_ps1[r2 + 1];
    float c0 = g_ps2[r2], c1 = g_ps2[r2 + 1];
    float M = fmaxf(m0, m1);
    float e0 = __expf(m0 - M), e1 = __expf(m1 - M);
    float S1 = a0 * e0 + a1 * e1;
    float S2 = (c0 + (m0 - M) * a0) * e0 + (c1 + (m1 - M) * a1) * e1;
    return S2 / S1 - logf(S1);
}

// ---------------------------------------------------------------------------
// K2: gates kernel. Grid 16 = (branch, batch); 512 threads.
// branch 0: entropy chain  -A concat -> We1/relu -> We2/sigmoid -> g_ew
// branch 1: mi chain       A_v+A_t   -> Wm1/relu -> Wm2/sigmoid -> g_mw
// Each warp computes 16 outputs with batched accumulators (high ILP).
// ---------------------------------------------------------------------------
__global__ __launch_bounds__(512) void gates_kernel(
    const float* __restrict__ We1, const float* __restrict__ be1,
    const float* __restrict__ We2, const float* __restrict__ be2,
    const float* __restrict__ Wm1, const float* __restrict__ bm1,
    const float* __restrict__ Wm2, const float* __restrict__ bm2)
{
    __shared__ float xs[512];
    __shared__ float h1[256];

    const int bid = blockIdx.x;
    const int branch = bid >> 3;
    const int b = bid & 7;
    const int tid = threadIdx.x;
    const int warp = tid >> 5, lane = tid & 31;

    if (tid < 256) {
        const int c = tid;
        float Av = mergeA((b * 256 + c) * 2);
        float At = mergeA(((8 + b) * 256 + c) * 2);
        if (branch == 0) {
            xs[c] = -Av;
            xs[256 + c] = -At;
        } else {
            xs[c] = Av + At;
        }
    }
    __syncthreads();

    const int j0 = warp * 16;

    // ---- layer 1 ----
    {
        const float* __restrict__ W1 = branch ? Wm1 : We1;
        const float* __restrict__ bb1 = branch ? bm1 : be1;
        float acc[16];
        #pragma unroll
        for (int q = 0; q < 16; q++) acc[q] = 0.f;
        if (branch == 0) {
            #pragma unroll
            for (int i = 0; i < 16; i++) {
                float x = xs[lane + 32 * i];
                #pragma unroll
                for (int q = 0; q < 16; q++)
                    acc[q] += W1[(j0 + q) * 512 + lane + 32 * i] * x;
            }
        } else {
            #pragma unroll
            for (int i = 0; i < 8; i++) {
                float x = xs[lane + 32 * i];
                #pragma unroll
                for (int q = 0; q < 16; q++)
                    acc[q] += W1[(j0 + q) * 256 + lane + 32 * i] * x;
            }
        }
        #pragma unroll
        for (int q = 0; q < 16; q++)
            #pragma unroll
            for (int off = 16; off; off >>= 1)
                acc[q] += __shfl_xor_sync(0xffffffffu, acc[q], off);
        if (lane == 0) {
            #pragma unroll
            for (int q = 0; q < 16; q++)
                h1[j0 + q] = fmaxf(acc[q] + bb1[j0 + q], 0.f);
        }
    }
    __syncthreads();

    // ---- layer 2 + sigmoid ----
    {
        const float* __restrict__ W2 = branch ? Wm2 : We2;
        const float* __restrict__ bb2 = branch ? bm2 : be2;
        float acc[16];
        #pragma unroll
        for (int q = 0; q < 16; q++) acc[q] = 0.f;
        #pragma unroll
        for (int i = 0; i < 8; i++) {
            float x = h1[lane + 32 * i];
            #pragma unroll
            for (int q = 0; q < 16; q++)
                acc[q] += W2[(j0 + q) * 256 + lane + 32 * i] * x;
        }
        #pragma unroll
        for (int q = 0; q < 16; q++)
            #pragma unroll
            for (int off = 16; off; off >>= 1)
                acc[q] += __shfl_xor_sync(0xffffffffu, acc[q], off);
        if (lane == 0) {
            float* out = branch ? g_mw : g_ew;
            #pragma unroll
            for (int q = 0; q < 16; q++)
                out[b * 256 + j0 + q] = sigmoidf(acc[q] + bb2[j0 + q]);
        }
    }
}

// ---------------------------------------------------------------------------
// K4: final conv, K=512 (vis half then text half), gates folded into B staging.
// Tile 64x64, 128 threads, per-thread 4x8 (f32x2), double-buffered.
// Grid (4,4,8) = 128 blocks. LDS ratio 1.5 (vs 2.0 before).
// ---------------------------------------------------------------------------
__global__ __launch_bounds__(128) void conv2_kernel(
    const float* __restrict__ Wf, const float* __restrict__ bf,
    const float* __restrict__ g2, const float* __restrict__ b2,
    const float* __restrict__ m2, const float* __restrict__ v2,
    float* __restrict__ out)
{
    __shared__ __align__(16) float As[2][8][72];
    __shared__ __align__(16) float Bs[2][8][64];
    __shared__ float sc[512];

    const int bm = blockIdx.x * 64;
    const int bn = blockIdx.y * 64;
    const int b = blockIdx.z;
    const int tid = threadIdx.x;
    const int tx = tid & 7, ty = tid >> 3;  // tx: 8 col-groups, ty: 16 row-groups

    #pragma unroll
    for (int l = tid; l < 256; l += 128) {
        float e = g_ew[b * 256 + l], m = g_mw[b * 256 + l];
        sc[l] = e * m;
        sc[l + 256] = (1.f - e) * m;
    }

    // A staging: thread -> (iA, kA): float4 along K
    const int iA = tid >> 1, kA = (tid & 1) * 4;
    const float* __restrict__ pA0 = Wf + (bm + iA) * 512 + kA;
    // B staging: thread -> (jB, nB): k-rows jB, jB+2, jB+4, jB+6
    const int nB = tid & 63, jB = tid >> 6;
    const float* __restrict__ Xv = g_trans + b * 65536 + bn + nB;
    const float* __restrict__ Xt = g_trans + (8 + b) * 65536 + bn + nB;

    float4 ra;
    float rb0, rb1, rb2, rb3;

    ra = *(const float4*)pA0;
    rb0 = Xv[jB * 256];       rb1 = Xv[(jB + 2) * 256];
    rb2 = Xv[(jB + 4) * 256]; rb3 = Xv[(jB + 6) * 256];
    __syncthreads();  // sc ready before use below
    As[0][kA][iA] = ra.x; As[0][kA + 1][iA] = ra.y;
    As[0][kA + 2][iA] = ra.z; As[0][kA + 3][iA] = ra.w;
    Bs[0][jB][nB] = rb0 * sc[jB];
    Bs[0][jB + 2][nB] = rb1 * sc[jB + 2];
    Bs[0][jB + 4][nB] = rb2 * sc[jB + 4];
    Bs[0][jB + 6][nB] = rb3 * sc[jB + 6];
    __syncthreads();

    ull acc[4][4];
    #pragma unroll
    for (int r = 0; r < 4; r++)
        #pragma unroll
        for (int p = 0; p < 4; p++) acc[r][p] = 0ull;

    int buf = 0;
    for (int step = 0; step < 64; step++) {
        const int c0n = (step + 1) * 8;
        if (step < 63) {
            ra = *(const float4*)(pA0 + c0n);
            const float* pb = (c0n < 256) ? (Xv + c0n * 256) : (Xt + (c0n - 256) * 256);
            rb0 = pb[jB * 256];       rb1 = pb[(jB + 2) * 256];
            rb2 = pb[(jB + 4) * 256]; rb3 = pb[(jB + 6) * 256];
        }
        #pragma unroll
        for (int kk = 0; kk < 8; kk++) {
            const float4 a4 = *(const float4*)&As[buf][kk][ty * 4];
            const ull ad0 = pk2(a4.x), ad1 = pk2(a4.y), ad2 = pk2(a4.z), ad3 = pk2(a4.w);
            const ulonglong2 bA = *(const ulonglong2*)&Bs[buf][kk][tx * 8];
            const ulonglong2 bB = *(const ulonglong2*)&Bs[buf][kk][tx * 8 + 4];
            fma2(acc[0][0], ad0, bA.x); fma2(acc[0][1], ad0, bA.y);
            fma2(acc[0][2], ad0, bB.x); fma2(acc[0][3], ad0, bB.y);
            fma2(acc[1][0], ad1, bA.x); fma2(acc[1][1], ad1, bA.y);
            fma2(acc[1][2], ad1, bB.x); fma2(acc[1][3], ad1, bB.y);
            fma2(acc[2][0], ad2, bA.x); fma2(acc[2][1], ad2, bA.y);
            fma2(acc[2][2], ad2, bB.x); fma2(acc[2][3], ad2, bB.y);
            fma2(acc[3][0], ad3, bA.x); fma2(acc[3][1], ad3, bA.y);
            fma2(acc[3][2], ad3, bB.x); fma2(acc[3][3], ad3, bB.y);
        }
        if (step < 63) {
            const int nb = buf ^ 1;
            As[nb][kA][iA] = ra.x; As[nb][kA + 1][iA] = ra.y;
            As[nb][kA + 2][iA] = ra.z; As[nb][kA + 3][iA] = ra.w;
            Bs[nb][jB][nB] = rb0 * sc[c0n + jB];
            Bs[nb][jB + 2][nB] = rb1 * sc[c0n + jB + 2];
            Bs[nb][jB + 4][nB] = rb2 * sc[c0n + jB + 4];
            Bs[nb][jB + 6][nB] = rb3 * sc[c0n + jB + 6];
        }
        __syncthreads();
        buf ^= 1;
    }

    #pragma unroll
    for (int r = 0; r < 4; r++) {
        const int o = bm + ty * 4 + r;
        const float s = g2[o] * rsqrtf(v2[o] + EPS_BN);
        const float sh = (bf[o] - m2[o]) * s + b2[o];
        float y[8];
        #pragma unroll
        for (int p = 0; p < 4; p++) {
            float2 v = upk(acc[r][p]);
            y[2 * p] = fmaxf(v.x * s + sh, 0.f);
            y[2 * p + 1] = fmaxf(v.y * s + sh, 0.f);
        }
        float* dst = &out[(b * 256 + o) * 256 + bn + tx * 8];
        *(float4*)dst = make_float4(y[0], y[1], y[2], y[3]);
        *(float4*)(dst + 4) = make_float4(y[4], y[5], y[6], y[7]);
    }
}

// ---------------------------------------------------------------------------
extern "C" void kernel_launch(void* const* d_in, const int* in_sizes, int n_in,
                              void* d_out, int out_size)
{
    const float* vis  = (const float*)d_in[0];
    const float* text = (const float*)d_in[1];
    const float* Wt   = (const float*)d_in[2];
    const float* bt   = (const float*)d_in[3];
    const float* g1   = (const float*)d_in[4];
    const float* b1   = (const float*)d_in[5];
    const float* m1   = (const float*)d_in[6];
    const float* v1   = (const float*)d_in[7];
    const float* We1  = (const float*)d_in[8];
    const float* be1  = (const float*)d_in[9];
    const float* We2  = (const float*)d_in[10];
    const float* be2  = (const float*)d_in[11];
    const float* Wm1  = (const float*)d_in[12];
    const float* bm1  = (const float*)d_in[13];
    const float* Wm2  = (const float*)d_in[14];
    const float* bm2  = (const float*)d_in[15];
    const float* Wf   = (const float*)d_in[16];
    const float* bf   = (const float*)d_in[17];
    const float* g2   = (const float*)d_in[18];
    const float* b2   = (const float*)d_in[19];
    const float* m2   = (const float*)d_in[20];
    const float* v2   = (const float*)d_in[21];
    float* out = (float*)d_out;

    conv1_kernel<<<dim3(4, 2, 16), 256>>>(vis, text, Wt, bt, g1, b1, m1, v1);
    gates_kernel<<<16, 512>>>(We1, be1, We2, be2, Wm1, bm1, Wm2, bm2);
    conv2_kernel<<<dim3(4, 4, 8), 128>>>(Wf, bf, g2, b2, m2, v2, out);
}

// round 14
// speedup vs baseline: 1.7436x; 1.7388x over previous
#include <cuda_runtime.h>
#include <cuda_bf16.h>
#include <mma.h>
#include <cstdint>

using namespace nvcuda;

#define EPS_BN 1e-5f
typedef uint32_t u32;

// ---------------- scratch (static; no allocation allowed) -------------------
__device__ u32   g_th32[2 * 8 * 256 * 256 / 2];  // conv1 out hi bf16, packed pairs
__device__ u32   g_tl32[2 * 8 * 256 * 256 / 2];  // conv1 out lo bf16, packed pairs
__device__ float g_pm[4096 * 2];                 // softmax partials (max) per (row, half)
__device__ float g_ps1[4096 * 2];                // sum e^(x-m)
__device__ float g_ps2[4096 * 2];                // sum (x-m)e^(x-m)
__device__ float g_ew[8 * 256];                  // entropy gate
__device__ float g_mw[8 * 256];                  // mi gate

__device__ __forceinline__ float sigmoidf(float x) { return 1.f / (1.f + __expf(-x)); }

__device__ __forceinline__ void split2(float x0, float x1, u32& h, u32& l) {
    __nv_bfloat16 h0 = __float2bfloat16(x0), h1 = __float2bfloat16(x1);
    __nv_bfloat16 l0 = __float2bfloat16(x0 - __bfloat162float(h0));
    __nv_bfloat16 l1 = __float2bfloat16(x1 - __bfloat162float(h1));
    h = (u32)__bfloat16_as_ushort(h0) | ((u32)__bfloat16_as_ushort(h1) << 16);
    l = (u32)__bfloat16_as_ushort(l0) | ((u32)__bfloat16_as_ushort(l1) << 16);
}

typedef wmma::fragment<wmma::matrix_a, 16, 16, 16, __nv_bfloat16, wmma::row_major> FragA;
typedef wmma::fragment<wmma::matrix_b, 16, 16, 16, __nv_bfloat16, wmma::row_major> FragB;
typedef wmma::fragment<wmma::accumulator, 16, 16, 16, float> FragC;

// smem layouts (bytes)
// conv1: Ah[64][136]b16, Al, Bh[128][136]b16, Bl; epilogue scratch = float[64][136] over Bh region
#define C1_AH 0
#define C1_AL 17408
#define C1_BH 34816
#define C1_BL 69632
#define C1_SMEM 104448
// conv2: Ah[64][136]b16, Al, Bh[128][72]b16, Bl, sc[512]f32; scratch = float[64][72] over Bh
#define C2_AH 0
#define C2_AL 17408
#define C2_BH 34816
#define C2_BL 53248
#define C2_SC 71680
#define C2_SMEM 73728

// ---------------------------------------------------------------------------
// conv1: Y = relu(BN(W @ X)); per CTA: M=64 (o), N=128 (n), K=256 (2 chunks).
// Grid (4 Mtiles, 2 n-halves, 16 zb) x 128 thr (4 warps, 2x2, warp tile 32x64).
// 3-pass bf16 hi/lo -> fp32 acc. Epilogue: BN+ReLU fp32, entropy half-row
// partials, packed hi|lo output for conv2.
// ---------------------------------------------------------------------------
__global__ __launch_bounds__(128) void conv1_wm(
    const float* __restrict__ vis, const float* __restrict__ text,
    const float* __restrict__ W, const float* __restrict__ bt,
    const float* __restrict__ g1, const float* __restrict__ b1,
    const float* __restrict__ m1, const float* __restrict__ v1)
{
    extern __shared__ char smem[];
    __nv_bfloat16* Ah = (__nv_bfloat16*)(smem + C1_AH);
    __nv_bfloat16* Al = (__nv_bfloat16*)(smem + C1_AL);
    __nv_bfloat16* Bh = (__nv_bfloat16*)(smem + C1_BH);
    __nv_bfloat16* Bl = (__nv_bfloat16*)(smem + C1_BL);

    const int tid = threadIdx.x, warp = tid >> 5;
    const int wm = warp >> 1, wn = warp & 1;
    const int bm = blockIdx.x * 64, n0 = blockIdx.y * 128, zb = blockIdx.z;
    const float* __restrict__ X =
        (zb >= 8) ? (text + (size_t)(zb - 8) * 65536) : (vis + (size_t)zb * 65536);

    FragC acc[2][4];
    #pragma unroll
    for (int i = 0; i < 2; i++)
        #pragma unroll
        for (int j = 0; j < 4; j++) wmma::fill_fragment(acc[i][j], 0.f);

    #pragma unroll 1
    for (int chunk = 0; chunk < 2; chunk++) {
        const int k0 = chunk * 128;
        // stage A = W[bm..bm+64)[k0..k0+128) hi/lo
        {
            const int r = tid >> 1, kh = (tid & 1) * 64;
            const float4* src = (const float4*)(W + (size_t)(bm + r) * 256 + k0 + kh);
            u32* rh = (u32*)(Ah + r * 136 + kh);
            u32* rl = (u32*)(Al + r * 136 + kh);
            #pragma unroll
            for (int i = 0; i < 16; i++) {
                float4 v = src[i];
                u32 h0, l0, h1, l1;
                split2(v.x, v.y, h0, l0);
                split2(v.z, v.w, h1, l1);
                rh[2 * i] = h0; rh[2 * i + 1] = h1;
                rl[2 * i] = l0; rl[2 * i + 1] = l1;
            }
        }
        // stage B = X[k0..k0+128)[n0..n0+128) hi/lo
        {
            const int r = tid;
            const float4* src = (const float4*)(X + (size_t)(k0 + r) * 256 + n0);
            u32* rh = (u32*)(Bh + r * 136);
            u32* rl = (u32*)(Bl + r * 136);
            #pragma unroll
            for (int i = 0; i < 32; i++) {
                float4 v = src[i];
                u32 h0, l0, h1, l1;
                split2(v.x, v.y, h0, l0);
                split2(v.z, v.w, h1, l1);
                rh[2 * i] = h0; rh[2 * i + 1] = h1;
                rl[2 * i] = l0; rl[2 * i + 1] = l1;
            }
        }
        __syncthreads();

        #pragma unroll
        for (int ks = 0; ks < 8; ks++) {
            FragA ah[2], al[2];
            #pragma unroll
            for (int i = 0; i < 2; i++) {
                wmma::load_matrix_sync(ah[i], Ah + (wm * 32 + 16 * i) * 136 + ks * 16, 136);
                wmma::load_matrix_sync(al[i], Al + (wm * 32 + 16 * i) * 136 + ks * 16, 136);
            }
            #pragma unroll
            for (int j = 0; j < 4; j++) {
                FragB bh, bl;
                wmma::load_matrix_sync(bh, Bh + (ks * 16) * 136 + wn * 64 + 16 * j, 136);
                wmma::load_matrix_sync(bl, Bl + (ks * 16) * 136 + wn * 64 + 16 * j, 136);
                #pragma unroll
                for (int i = 0; i < 2; i++) {
                    wmma::mma_sync(acc[i][j], ah[i], bh, acc[i][j]);
                    wmma::mma_sync(acc[i][j], ah[i], bl, acc[i][j]);
                    wmma::mma_sync(acc[i][j], al[i], bh, acc[i][j]);
                }
            }
        }
        __syncthreads();
    }

    // ---- epilogue: dump acc to scratch, BN+ReLU, entropy partial, store ----
    float* scr = (float*)(smem + C1_BH);  // 64 x 136 fp32
    #pragma unroll
    for (int i = 0; i < 2; i++)
        #pragma unroll
        for (int j = 0; j < 4; j++)
            wmma::store_matrix_sync(scr + (wm * 32 + 16 * i) * 136 + wn * 64 + 16 * j,
                                    acc[i][j], 136, wmma::mem_row_major);
    __syncthreads();

    {
        const int row = tid >> 1, ch = (tid & 1) * 64;
        const int o = bm + row;
        const float s = g1[o] * rsqrtf(v1[o] + EPS_BN);
        const float sh = (bt[o] - m1[o]) * s + b1[o];
        float y[64];
        #pragma unroll
        for (int j = 0; j < 64; j++)
            y[j] = fmaxf(fmaf(scr[row * 136 + ch + j], s, sh), 0.f);

        // packed hi|lo store (u32 = 2 bf16)
        u32* dh = g_th32 + ((size_t)zb * 65536 + (size_t)o * 256 + n0 + ch) / 2;
        u32* dl = g_tl32 + ((size_t)zb * 65536 + (size_t)o * 256 + n0 + ch) / 2;
        #pragma unroll
        for (int g = 0; g < 8; g++) {
            u32 hw[4], lw[4];
            #pragma unroll
            for (int p = 0; p < 4; p++)
                split2(y[8 * g + 2 * p], y[8 * g + 2 * p + 1], hw[p], lw[p]);
            *(uint4*)(dh + 4 * g) = make_uint4(hw[0], hw[1], hw[2], hw[3]);
            *(uint4*)(dl + 4 * g) = make_uint4(lw[0], lw[1], lw[2], lw[3]);
        }

        // entropy partial over this 128-wide half-row (2 threads x 64 vals)
        float mx = y[0];
        #pragma unroll
        for (int j = 1; j < 64; j++) mx = fmaxf(mx, y[j]);
        mx = fmaxf(mx, __shfl_xor_sync(0xffffffffu, mx, 1));
        float s1 = 0.f, s2 = 0.f;
        #pragma unroll
        for (int j = 0; j < 64; j++) {
            float u = y[j] - mx;
            float e = __expf(u);
            s1 += e;
            s2 += u * e;
        }
        s1 += __shfl_xor_sync(0xffffffffu, s1, 1);
        s2 += __shfl_xor_sync(0xffffffffu, s2, 1);
        if ((tid & 1) == 0) {
            const int idx = (zb * 256 + o) * 2 + blockIdx.y;
            g_pm[idx] = mx;
            g_ps1[idx] = s1;
            g_ps2[idx] = s2;
        }
    }
}

// ---------------------------------------------------------------------------
// gates: exact 2-way LSE merge -> A = S2/S1 - ln S1; entropy + mi MLP chains.
// (proven R6 structure)
// ---------------------------------------------------------------------------
__device__ __forceinline__ float mergeA(int r2)
{
    float m0 = g_pm[r2], m1 = g_pm[r2 + 1];
    float a0 = g_ps1[r2], a1 = g_ps1[r2 + 1];
    float c0 = g_ps2[r2], c1 = g_ps2[r2 + 1];
    float M = fmaxf(m0, m1);
    float e0 = __expf(m0 - M), e1 = __expf(m1 - M);
    float S1 = a0 * e0 + a1 * e1;
    float S2 = (c0 + (m0 - M) * a0) * e0 + (c1 + (m1 - M) * a1) * e1;
    return S2 / S1 - logf(S1);
}

__global__ __launch_bounds__(512) void gates_kernel(
    const float* __restrict__ We1, const float* __restrict__ be1,
    const float* __restrict__ We2, const float* __restrict__ be2,
    const float* __restrict__ Wm1, const float* __restrict__ bm1,
    const float* __restrict__ Wm2, const float* __restrict__ bm2)
{
    __shared__ float xs[512];
    __shared__ float h1[256];

    const int bid = blockIdx.x;
    const int branch = bid >> 3, b = bid & 7;
    const int tid = threadIdx.x, warp = tid >> 5, lane = tid & 31;

    if (tid < 256) {
        const int c = tid;
        float Av = mergeA((b * 256 + c) * 2);
        float At = mergeA(((8 + b) * 256 + c) * 2);
        if (branch == 0) { xs[c] = -Av; xs[256 + c] = -At; }
        else              xs[c] = Av + At;
    }
    __syncthreads();

    const int j0 = warp * 16;
    {
        const float* __restrict__ W1 = branch ? Wm1 : We1;
        const float* __restrict__ bb1 = branch ? bm1 : be1;
        float acc[16];
        #pragma unroll
        for (int q = 0; q < 16; q++) acc[q] = 0.f;
        if (branch == 0) {
            #pragma unroll
            for (int i = 0; i < 16; i++) {
                float x = xs[lane + 32 * i];
                #pragma unroll
                for (int q = 0; q < 16; q++) acc[q] += W1[(j0 + q) * 512 + lane + 32 * i] * x;
            }
        } else {
            #pragma unroll
            for (int i = 0; i < 8; i++) {
                float x = xs[lane + 32 * i];
                #pragma unroll
                for (int q = 0; q < 16; q++) acc[q] += W1[(j0 + q) * 256 + lane + 32 * i] * x;
            }
        }
        #pragma unroll
        for (int q = 0; q < 16; q++)
            #pragma unroll
            for (int off = 16; off; off >>= 1) acc[q] += __shfl_xor_sync(0xffffffffu, acc[q], off);
        if (lane == 0) {
            #pragma unroll
            for (int q = 0; q < 16; q++) h1[j0 + q] = fmaxf(acc[q] + bb1[j0 + q], 0.f);
        }
    }
    __syncthreads();
    {
        const float* __restrict__ W2 = branch ? Wm2 : We2;
        const float* __restrict__ bb2 = branch ? bm2 : be2;
        float acc[16];
        #pragma unroll
        for (int q = 0; q < 16; q++) acc[q] = 0.f;
        #pragma unroll
        for (int i = 0; i < 8; i++) {
            float x = h1[lane + 32 * i];
            #pragma unroll
            for (int q = 0; q < 16; q++) acc[q] += W2[(j0 + q) * 256 + lane + 32 * i] * x;
        }
        #pragma unroll
        for (int q = 0; q < 16; q++)
            #pragma unroll
            for (int off = 16; off; off >>= 1) acc[q] += __shfl_xor_sync(0xffffffffu, acc[q], off);
        if (lane == 0) {
            float* out = branch ? g_mw : g_ew;
            #pragma unroll
            for (int q = 0; q < 16; q++) out[b * 256 + j0 + q] = sigmoidf(acc[q] + bb2[j0 + q]);
        }
    }
}

// ---------------------------------------------------------------------------
// conv2: out = relu(BN((Wf*sc) @ T)); per CTA M=64, N=64, K=512 (4 chunks).
// Grid (4 Mtiles, 4 n-tiles, 8 b) x 128 thr (4 warps 2x2, warp tile 32x32).
// Gates folded into A in fp32 (exact), then hi/lo split. B = copy of packed
// hi|lo conv1 output (chunks 0,1 = vis; 2,3 = text).
// ---------------------------------------------------------------------------
__global__ __launch_bounds__(128) void conv2_wm(
    const float* __restrict__ Wf, const float* __restrict__ bf,
    const float* __restrict__ g2, const float* __restrict__ b2,
    const float* __restrict__ m2, const float* __restrict__ v2,
    float* __restrict__ out)
{
    extern __shared__ char smem[];
    __nv_bfloat16* Ah = (__nv_bfloat16*)(smem + C2_AH);
    __nv_bfloat16* Al = (__nv_bfloat16*)(smem + C2_AL);
    __nv_bfloat16* Bh = (__nv_bfloat16*)(smem + C2_BH);
    __nv_bfloat16* Bl = (__nv_bfloat16*)(smem + C2_BL);
    float* sc = (float*)(smem + C2_SC);

    const int tid = threadIdx.x, warp = tid >> 5;
    const int wm = warp >> 1, wn = warp & 1;
    const int bm = blockIdx.x * 64, n0 = blockIdx.y * 64, b = blockIdx.z;

    #pragma unroll
    for (int i = 0; i < 2; i++) {
        const int c = tid + 128 * i;
        float e = g_ew[b * 256 + c], m = g_mw[b * 256 + c];
        sc[c] = e * m;
        sc[c + 256] = (1.f - e) * m;
    }
    __syncthreads();

    FragC acc[2][2];
    #pragma unroll
    for (int i = 0; i < 2; i++)
        #pragma unroll
        for (int j = 0; j < 2; j++) wmma::fill_fragment(acc[i][j], 0.f);

    #pragma unroll 1
    for (int chunk = 0; chunk < 4; chunk++) {
        // stage A = Wf*sc, rows bm..bm+64, cols chunk*128..+128, hi/lo
        {
            const int r = tid >> 1, kh = (tid & 1) * 64;
            const float4* src = (const float4*)(Wf + (size_t)(bm + r) * 512 + chunk * 128 + kh);
            const float4* gsc = (const float4*)(sc + chunk * 128 + kh);
            u32* rh = (u32*)(Ah + r * 136 + kh);
            u32* rl = (u32*)(Al + r * 136 + kh);
            #pragma unroll
            for (int i = 0; i < 16; i++) {
                float4 v = src[i];
                float4 g = gsc[i];
                u32 h0, l0, h1, l1;
                split2(v.x * g.x, v.y * g.y, h0, l0);
                split2(v.z * g.z, v.w * g.w, h1, l1);
                rh[2 * i] = h0; rh[2 * i + 1] = h1;
                rl[2 * i] = l0; rl[2 * i + 1] = l1;
            }
        }
        // stage B: copy packed hi|lo rows (k = channel), cols n0..n0+64
        {
            const int r = tid;
            const int t2 = chunk >> 1;
            const int c = (chunk & 1) * 128 + r;
            const size_t off = ((size_t)(t2 * 8 + b) * 65536 + (size_t)c * 256 + n0) / 2;
            const uint4* sh4 = (const uint4*)(g_th32 + off);
            const uint4* sl4 = (const uint4*)(g_tl32 + off);
            uint4* rh = (uint4*)(Bh + r * 72);
            uint4* rl = (uint4*)(Bl + r * 72);
            #pragma unroll
            for (int i = 0; i < 8; i++) { rh[i] = sh4[i]; rl[i] = sl4[i]; }
        }
        __syncthreads();

        #pragma unroll
        for (int ks = 0; ks < 8; ks++) {
            FragA ah[2], al[2];
            #pragma unroll
            for (int i = 0; i < 2; i++) {
                wmma::load_matrix_sync(ah[i], Ah + (wm * 32 + 16 * i) * 136 + ks * 16, 136);
                wmma::load_matrix_sync(al[i], Al + (wm * 32 + 16 * i) * 136 + ks * 16, 136);
            }
            #pragma unroll
            for (int j = 0; j < 2; j++) {
                FragB bh, bl;
                wmma::load_matrix_sync(bh, Bh + (ks * 16) * 72 + wn * 32 + 16 * j, 72);
                wmma::load_matrix_sync(bl, Bl + (ks * 16) * 72 + wn * 32 + 16 * j, 72);
                #pragma unroll
                for (int i = 0; i < 2; i++) {
                    wmma::mma_sync(acc[i][j], ah[i], bh, acc[i][j]);
                    wmma::mma_sync(acc[i][j], ah[i], bl, acc[i][j]);
                    wmma::mma_sync(acc[i][j], al[i], bh, acc[i][j]);
                }
            }
        }
        __syncthreads();
    }

    // ---- epilogue ----
    float* scr = (float*)(smem + C2_BH);  // 64 x 72 fp32
    #pragma unroll
    for (int i = 0; i < 2; i++)
        #pragma unroll
        for (int j = 0; j < 2; j++)
            wmma::store_matrix_sync(scr + (wm * 32 + 16 * i) * 72 + wn * 32 + 16 * j,
                                    acc[i][j], 72, wmma::mem_row_major);
    __syncthreads();

    {
        const int row = tid >> 1, ch = (tid & 1) * 32;
        const int o = bm + row;
        const float s = g2[o] * rsqrtf(v2[o] + EPS_BN);
        const float sh = (bf[o] - m2[o]) * s + b2[o];
        float* dst = out + (size_t)(b * 256 + o) * 256 + n0 + ch;
        #pragma unroll
        for (int p = 0; p < 8; p++) {
            float4 y;
            y.x = fmaxf(fmaf(scr[row * 72 + ch + 4 * p + 0], s, sh), 0.f);
            y.y = fmaxf(fmaf(scr[row * 72 + ch + 4 * p + 1], s, sh), 0.f);
            y.z = fmaxf(fmaf(scr[row * 72 + ch + 4 * p + 2], s, sh), 0.f);
            y.w = fmaxf(fmaf(scr[row * 72 + ch + 4 * p + 3], s, sh), 0.f);
            *(float4*)(dst + 4 * p) = y;
        }
    }
}

// ---------------------------------------------------------------------------
extern "C" void kernel_launch(void* const* d_in, const int* in_sizes, int n_in,
                              void* d_out, int out_size)
{
    const float* vis  = (const float*)d_in[0];
    const float* text = (const float*)d_in[1];
    const float* Wt   = (const float*)d_in[2];
    const float* bt   = (const float*)d_in[3];
    const float* g1   = (const float*)d_in[4];
    const float* b1   = (const float*)d_in[5];
    const float* m1   = (const float*)d_in[6];
    const float* v1   = (const float*)d_in[7];
    const float* We1  = (const float*)d_in[8];
    const float* be1  = (const float*)d_in[9];
    const float* We2  = (const float*)d_in[10];
    const float* be2  = (const float*)d_in[11];
    const float* Wm1  = (const float*)d_in[12];
    const float* bm1  = (const float*)d_in[13];
    const float* Wm2  = (const float*)d_in[14];
    const float* bm2  = (const float*)d_in[15];
    const float* Wf   = (const float*)d_in[16];
    const float* bf   = (const float*)d_in[17];
    const float* g2   = (const float*)d_in[18];
    const float* b2   = (const float*)d_in[19];
    const float* m2   = (const float*)d_in[20];
    const float* v2   = (const float*)d_in[21];
    float* out = (float*)d_out;

    static bool attr_done = false;
    if (!attr_done) {
        cudaFuncSetAttribute(conv1_wm, cudaFuncAttributeMaxDynamicSharedMemorySize, C1_SMEM);
        cudaFuncSetAttribute(conv2_wm, cudaFuncAttributeMaxDynamicSharedMemorySize, C2_SMEM);
        attr_done = true;
    }

    conv1_wm<<<dim3(4, 2, 16), 128, C1_SMEM>>>(vis, text, Wt, bt, g1, b1, m1, v1);
    gates_kernel<<<16, 512>>>(We1, be1, We2, be2, Wm1, bm1, Wm2, bm2);
    conv2_wm<<<dim3(4, 4, 8), 128, C2_SMEM>>>(Wf, bf, g2, b2, m2, v2, out);
}